// round 5
// baseline (speedup 1.0000x reference)
#include <cuda_runtime.h>
#include <cuda_bf16.h>
#include <cstdint>

#define LEN_M   131328
#define D_H     256
#define N_MC    64
#define DDP1    513
#define NROWS   4096
#define NCOL    512        // 2*D_H : C = [A|B] = [x@m | x@s]
#define KP      512        // MMA K (col 512 handled as rank-1 update)
#define NCHUNK  8          // 512 / 64
#define BKB     128        // bytes per smem row (64 bf16) = SW128 atom

// -------- persistent scratch (no allocs allowed) ---------------------------
__device__ __align__(128) __nv_bfloat16 g_xh[NROWS * KP];
__device__ __align__(128) __nv_bfloat16 g_xl[NROWS * KP];
__device__ __align__(128) __nv_bfloat16 g_bh[NCOL * KP];   // B[n][k] = W[k][n]
__device__ __align__(128) __nv_bfloat16 g_bl[NCOL * KP];
__device__ __align__(128) float g_x512[NROWS];
__device__ __align__(128) float g_w512[NCOL];
__device__ __align__(128) float g_C[NROWS * NCOL];

// -------- PTX helpers (arch-neutral: LDSM / HMMA / LDGSTS only) ------------
__device__ __forceinline__ uint32_t s2u(const void* p) {
    uint32_t a;
    asm("{ .reg .u64 t; cvta.to.shared.u64 t, %1; cvt.u32.u64 %0, t; }"
        : "=r"(a) : "l"(p));
    return a;
}
#define SW128(o) ((o) ^ (((o) >> 3) & 0x70))

#define LDSM_X4(r, a)                                                         \
    asm volatile("ldmatrix.sync.aligned.m8n8.x4.shared.b16 {%0,%1,%2,%3}, [%4];" \
        : "=r"((r)[0]), "=r"((r)[1]), "=r"((r)[2]), "=r"((r)[3]) : "r"(a))

#define MMA16816(d, a, b)                                                     \
    asm volatile("mma.sync.aligned.m16n8k16.row.col.f32.bf16.bf16.f32 "       \
        "{%0,%1,%2,%3}, {%4,%5,%6,%7}, {%8,%9}, {%0,%1,%2,%3};"               \
        : "+f"((d)[0]), "+f"((d)[1]), "+f"((d)[2]), "+f"((d)[3])              \
        : "r"((a)[0]), "r"((a)[1]), "r"((a)[2]), "r"((a)[3]),                 \
          "r"((b)[0]), "r"((b)[1]))

// -------- Kernel 1: fused prep (weights + x -> bf16 splits) -----------------
#define NW_ELEMS (NCOL * DDP1)          // 262656
#define NX_ELEMS (NROWS * DDP1)         // 2101248
#define PREP_TOT (NW_ELEMS + NX_ELEMS)

__global__ void prep_all(const float* __restrict__ params,
                         const float* __restrict__ x,
                         float* __restrict__ out_m, float* __restrict__ out_v) {
    int idx = blockIdx.x * blockDim.x + threadIdx.x;
    if (idx < NW_ELEMS) {
        int c = idx / DDP1;
        int d = idx - c * DDP1;
        int h = c & 255;
        int i = d * 256 + h;
        float w;
        if (c < 256) {
            float m = params[i];
            out_m[i] = m;
            w = m;
        } else {
            float v = fmaxf(params[LEN_M + i], 0.0f) + 1e-6f;
            out_v[i] = v;
            w = sqrtf(v);
        }
        if (d == 512) { g_w512[c] = w; return; }
        __nv_bfloat16 hi = __float2bfloat16(w);
        __nv_bfloat16 lo = __float2bfloat16(w - __bfloat162float(hi));
        g_bh[c * KP + d] = hi;
        g_bl[c * KP + d] = lo;
    } else if (idx < PREP_TOT) {
        int j = idx - NW_ELEMS;
        int n = j / DDP1;
        int k = j - n * DDP1;
        float v = x[j];
        if (k == 512) { g_x512[n] = v; return; }
        __nv_bfloat16 hi = __float2bfloat16(v);
        __nv_bfloat16 lo = __float2bfloat16(v - __bfloat162float(hi));
        g_xh[n * KP + k] = hi;
        g_xl[n * KP + k] = lo;
    }
}

// -------- Kernel 2: HMMA GEMM  C[4096,512] = x @ W  (bf16x3) ----------------
// grid (2, 64): block tile 64(M) x 256(N), 8 warps as 1(M)x8(N) -> 64x32/warp
// K = 8 chunks of 64 bf16 (128B SW128 rows), cp.async double-buffered.
#define TILE_A_B 8192                   // 64x64 bf16 tile
#define TILE_B_B 32768                  // 256x64 bf16 tile
#define CHSET_B  (2 * TILE_A_B + 2 * TILE_B_B)   // Ah | Al | Bh | Bl = 80KB
#define GSMEM    (1024 + 2 * CHSET_B)   // sw512 + 2 buffers = 161KB

__global__ __launch_bounds__(256, 1) void gemm_mma() {
    extern __shared__ __align__(1024) char smem[];
    const uint32_t sb = s2u(smem);
    float* sw512 = (float*)smem;          // 256 floats: W[512, colBase..+255]
    const uint32_t TB = sb + 1024;

    const int tid  = threadIdx.x;
    const int lane = tid & 31;
    const int warp = tid >> 5;
    const int wn = warp;                  // 0..7  (N eighth, 32 cols)
    const int rowBase = blockIdx.y * 64;
    const int colBase = blockIdx.x * 256;

    sw512[tid] = g_w512[colBase + tid];   // 256 threads, 256 floats

    float acc[4][4][4];
    #pragma unroll
    for (int mi = 0; mi < 4; mi++)
        #pragma unroll
        for (int nj = 0; nj < 4; nj++)
            #pragma unroll
            for (int q = 0; q < 4; q++)
                acc[mi][nj][q] = 0.0f;

    // issue one K-chunk (c) of all 4 tiles into buffer `buf` via cp.async
    auto issue_chunk = [&](int c, int buf) {
        const uint32_t tb = TB + buf * CHSET_B;
        // A tiles: 64 rows x 8 16B-slots = 512 slots each
        #pragma unroll
        for (int t = 0; t < 2; t++) {
            const char* gbase = t ? (const char*)g_xl : (const char*)g_xh;
            #pragma unroll
            for (int i = 0; i < 2; i++) {
                int q = tid + i * 256;
                int r = q >> 3, s = q & 7;
                const char* gp = gbase + (size_t)(rowBase + r) * (KP * 2)
                               + c * BKB + s * 16;
                uint32_t sp = tb + t * TILE_A_B + SW128(r * BKB + s * 16);
                asm volatile("cp.async.cg.shared.global [%0], [%1], 16;"
                             :: "r"(sp), "l"(gp));
            }
        }
        // B tiles: 256 rows x 8 slots = 2048 slots each
        #pragma unroll
        for (int t = 0; t < 2; t++) {
            const char* gbase = t ? (const char*)g_bl : (const char*)g_bh;
            #pragma unroll
            for (int i = 0; i < 8; i++) {
                int q = tid + i * 256;
                int r = q >> 3, s = q & 7;
                const char* gp = gbase + (size_t)(colBase + r) * (KP * 2)
                               + c * BKB + s * 16;
                uint32_t sp = tb + 2 * TILE_A_B + t * TILE_B_B
                            + SW128(r * BKB + s * 16);
                asm volatile("cp.async.cg.shared.global [%0], [%1], 16;"
                             :: "r"(sp), "l"(gp));
            }
        }
        asm volatile("cp.async.commit_group;" ::: "memory");
    };

    issue_chunk(0, 0);

    for (int c = 0; c < NCHUNK; c++) {
        const int buf = c & 1;
        if (c + 1 < NCHUNK) {
            issue_chunk(c + 1, buf ^ 1);
            asm volatile("cp.async.wait_group 1;" ::: "memory");
        } else {
            asm volatile("cp.async.wait_group 0;" ::: "memory");
        }
        __syncthreads();

        const uint32_t Ah = TB + buf * CHSET_B;
        const uint32_t Al = Ah + TILE_A_B;
        const uint32_t Bh = Al + TILE_A_B;
        const uint32_t Bl = Bh + TILE_B_B;

        #pragma unroll
        for (int s = 0; s < 4; s++) {        // four k16 steps per chunk
            const int k0 = s * 16;
            uint32_t ah[4][4], al[4][4], bhf[4][2], blf[4][2];

            #pragma unroll
            for (int mi = 0; mi < 4; mi++) {  // A frags: 16x16 per ldmatrix.x4
                int row = mi * 16 + (lane & 15);
                int col = k0 + ((lane >> 4) << 3);
                uint32_t off = SW128(row * BKB + col * 2);
                LDSM_X4(ah[mi], Ah + off);
                LDSM_X4(al[mi], Al + off);
            }
            #pragma unroll
            for (int p = 0; p < 2; p++) {     // B frags: n16xk16 per ldmatrix.x4
                int row = wn * 32 + p * 16 + (lane & 7) + ((lane & 16) >> 1);
                int col = k0 + (lane & 8);
                uint32_t off = SW128(row * BKB + col * 2);
                uint32_t r[4];
                LDSM_X4(r, Bh + off);
                bhf[p * 2][0] = r[0]; bhf[p * 2][1] = r[1];
                bhf[p * 2 + 1][0] = r[2]; bhf[p * 2 + 1][1] = r[3];
                LDSM_X4(r, Bl + off);
                blf[p * 2][0] = r[0]; blf[p * 2][1] = r[1];
                blf[p * 2 + 1][0] = r[2]; blf[p * 2 + 1][1] = r[3];
            }

            #pragma unroll
            for (int mi = 0; mi < 4; mi++)
                #pragma unroll
                for (int nj = 0; nj < 4; nj++) {
                    MMA16816(acc[mi][nj], ah[mi], bhf[nj]);   // xh*wh
                    MMA16816(acc[mi][nj], ah[mi], blf[nj]);   // xh*wl
                    MMA16816(acc[mi][nj], al[mi], bhf[nj]);   // xl*wh
                }
        }
        __syncthreads();                     // done reading buf before reuse
    }

    // epilogue: rank-1 update (K column 512) + store fp32
    #pragma unroll
    for (int mi = 0; mi < 4; mi++) {
        int r0 = rowBase + mi * 16 + (lane >> 2);
        float xv0 = g_x512[r0];
        float xv1 = g_x512[r0 + 8];
        #pragma unroll
        for (int nj = 0; nj < 4; nj++) {
            int cl = wn * 32 + nj * 8 + ((lane & 3) << 1);
            float w0 = sw512[cl], w1 = sw512[cl + 1];
            float2 v0 = { acc[mi][nj][0] + xv0 * w0, acc[mi][nj][1] + xv0 * w1 };
            float2 v1 = { acc[mi][nj][2] + xv1 * w0, acc[mi][nj][3] + xv1 * w1 };
            *(float2*)&g_C[(size_t)r0 * NCOL + colBase + cl]       = v0;
            *(float2*)&g_C[(size_t)(r0 + 8) * NCOL + colBase + cl] = v1;
        }
    }
}

// -------- Kernel 3: epilogue  pred[n,mc] -----------------------------------
// Thread = (n, mc); vectorized over h (pairs packed as f32x2, NO packing MOVs)
typedef unsigned long long ull;
union F4U { float4 f; ulonglong2 u; };
union F2U { float2 f; ull u; };

__device__ __forceinline__ ull fma2(ull a, ull b, ull c) {
    ull r; asm("fma.rn.f32x2 %0, %1, %2, %3;" : "=l"(r) : "l"(a), "l"(b), "l"(c));
    return r;
}

__global__ __launch_bounds__(512) void epi_kernel(const float* __restrict__ W1,
                                                  const float* __restrict__ eps,
                                                  float* __restrict__ out_pred) {
    __shared__ float sAB[8][512];   // 8 rows x [A(256) | B(256)]
    __shared__ float sW[256];       // W1[h+1]
    __shared__ float sw0;

    const int tid = threadIdx.x;
    const int rg  = tid >> 6;       // row within block (0..7)
    const int mc  = tid & 63;
    const int n   = blockIdx.x * 8 + rg;

    // load this row's 512 floats (64 threads x 2 float4 each)
    const float4* src = (const float4*)&g_C[(size_t)n * NCOL];
    float4* dst = (float4*)sAB[rg];
    dst[mc]      = src[mc];
    dst[mc + 64] = src[mc + 64];
    if (tid < 256) sW[tid] = W1[tid + 1];
    if (tid == 0) sw0 = W1[0];
    __syncthreads();

    F2U e2u; e2u.f.x = eps[mc]; e2u.f.y = e2u.f.x;
    const ull e2 = e2u.u;

    const F4U* A4 = (const F4U*)&sAB[rg][0];
    const F4U* B4 = (const F4U*)&sAB[rg][256];
    const F4U* W4 = (const F4U*)sW;

    ull acc0 = 0ull, acc1 = 0ull;

    #pragma unroll 8
    for (int i = 0; i < 64; i++) {   // 4 h per iteration
        F4U a = A4[i], b = B4[i], w = W4[i];
        F2U t0, t1;
        t0.u = fma2(e2, b.u.x, a.u.x);           // (a0+e*b0, a1+e*b1)
        t1.u = fma2(e2, b.u.y, a.u.y);
        t0.f.x = fmaxf(t0.f.x, 0.0f); t0.f.y = fmaxf(t0.f.y, 0.0f);
        t1.f.x = fmaxf(t1.f.x, 0.0f); t1.f.y = fmaxf(t1.f.y, 0.0f);
        acc0 = fma2(t0.u, w.u.x, acc0);
        acc1 = fma2(t1.u, w.u.y, acc1);
    }

    F2U r0, r1; r0.u = acc0; r1.u = acc1;
    out_pred[n * N_MC + mc] = sw0 + ((r0.f.x + r0.f.y) + (r1.f.x + r1.f.y));
}

// ---------------------------------------------------------------------------
extern "C" void kernel_launch(void* const* d_in, const int* in_sizes, int n_in,
                              void* d_out, int out_size) {
    const float* params = (const float*)d_in[0];
    const float* W1     = (const float*)d_in[1];
    const float* x      = (const float*)d_in[2];
    const float* eps    = (const float*)d_in[3];

    float* out      = (float*)d_out;
    float* out_pred = out;
    float* out_m    = out + NROWS * N_MC;
    float* out_v    = out_m + LEN_M;

    cudaFuncSetAttribute(gemm_mma, cudaFuncAttributeMaxDynamicSharedMemorySize, GSMEM);

    prep_all<<<(PREP_TOT + 255) / 256, 256>>>(params, x, out_m, out_v);
    gemm_mma<<<dim3(2, 64), 256, GSMEM>>>();
    epi_kernel<<<NROWS / 8, 512>>>(W1, eps, out_pred);
}